// round 6
// baseline (speedup 1.0000x reference)
#include <cuda_runtime.h>
#include <cuda_fp16.h>
#include <math.h>
#include <cstdint>

// ---------------- problem constants ----------------
#define BQ   4096
#define NU   100000
#define DIM  128
#define TOPK 5
#define K1   6
#define NSPLIT 4
#define NPS   25000                    // users per split
#define TM 128                         // queries per CTA
#define TN 128                         // users per tile
#define QB (BQ / TM)                   // 32
#define NTILES ((NPS + TN - 1) / TN)   // 196 (last tile: 40 valid, 88 pad)
#define PADROWS (NTILES * TN - NPS)    // 88
#define CAND 12
#define NCAND (NSPLIT * CAND)          // 48
#define SP_U32 130                     // sims pitch (u32), even for int2 stores
#define INT_MIN_V (-2147483647 - 1)

// ---------------- device scratch -------------------------------------------
__device__ float    g_ue_n[(size_t)NU * DIM];
__device__ float    g_q_n[(size_t)BQ * DIM];
__device__ uint32_t g_ubsw[(size_t)NSPLIT * NTILES * 4096];  // pre-swizzled s8 tiles (16KB each)
__device__ uint32_t g_qi8[(size_t)BQ * 32];                  // s8 queries, row-major packed
__device__ int      g_ci[(size_t)BQ * NCAND];

// ---------------- helpers ---------------------------------------------------
static __device__ __forceinline__ uint32_t smem_u32(const void* p) {
    uint32_t a;
    asm("{ .reg .u64 t; cvta.to.shared.u64 t, %1; cvt.u32.u64 %0, t; }" : "=r"(a) : "l"(p));
    return a;
}
static __device__ __forceinline__ void ldsm_x4(uint32_t addr, uint32_t r[4]) {
    asm volatile("ldmatrix.sync.aligned.m8n8.x4.shared.b16 {%0,%1,%2,%3}, [%4];"
                 : "=r"(r[0]), "=r"(r[1]), "=r"(r[2]), "=r"(r[3]) : "r"(addr));
}
static __device__ __forceinline__ void mma_s8(int c[4], const uint32_t a[4],
                                              uint32_t b0, uint32_t b1) {
    asm volatile("mma.sync.aligned.m16n8k32.row.col.s32.s8.s8.s32 "
                 "{%0,%1,%2,%3}, {%4,%5,%6,%7}, {%8,%9}, {%0,%1,%2,%3};"
                 : "+r"(c[0]), "+r"(c[1]), "+r"(c[2]), "+r"(c[3])
                 : "r"(a[0]), "r"(a[1]), "r"(a[2]), "r"(a[3]), "r"(b0), "r"(b1));
}
static __device__ __forceinline__ void bulk_ld(uint32_t dst, const void* src,
                                               uint32_t bytes, uint32_t mbar) {
    asm volatile("cp.async.bulk.shared::cluster.global.mbarrier::complete_tx::bytes "
                 "[%0], [%1], %2, [%3];"
                 :: "r"(dst), "l"(src), "r"(bytes), "r"(mbar) : "memory");
}
#define MBARRIER_INIT(addr, cnt) \
    asm volatile("mbarrier.init.shared.b64 [%0], %1;" :: "r"((uint32_t)(addr)), "r"((uint32_t)(cnt)) : "memory")
#define MBARRIER_EXPECT_TX(addr, bytes) \
    asm volatile("mbarrier.arrive.expect_tx.shared.b64 _, [%0], %1;" :: "r"((uint32_t)(addr)), "r"((uint32_t)(bytes)) : "memory")
#define MBARRIER_WAIT_PARITY(mbar_addr, parity) do { \
    uint32_t _mbar = (uint32_t)(mbar_addr); \
    uint32_t _par = (uint32_t)(parity); \
    uint32_t _done; \
    asm volatile("{\n\t.reg .pred p;\n\t" \
        "mbarrier.try_wait.parity.acquire.cta.shared::cta.b64 p, [%1], %2;\n\t" \
        "selp.b32 %0, 1, 0, p;\n\t}" : "=r"(_done) : "r"(_mbar), "r"(_par) : "memory"); \
    if (!_done) { \
        asm volatile("{\n\t.reg .pred P1;\n\t" \
            "WAIT_LOOP_%=:\n\t" \
            "mbarrier.try_wait.parity.acquire.cta.shared::cta.b64 P1, [%0], %1, 0x989680;\n\t" \
            "@P1 bra.uni WAIT_DONE_%=;\n\t" \
            "bra.uni WAIT_LOOP_%=;\n\t" \
            "WAIT_DONE_%=:\n\t}" :: "r"(_mbar), "r"(_par) : "memory"); \
    } \
} while (0)

// swizzled byte offset inside a [128 rows x 128B] s8 tile (16B chunks, XOR by row)
static __device__ __forceinline__ uint32_t tile_off8(int r, int chunk) {
    return (uint32_t)(r * 128 + ((chunk ^ (r & 7)) << 4));
}

// ---------------- Kernel A: normalize + s8 quantize (+ pre-swizzle users) ---
__global__ void prep_kernel(const float* __restrict__ q, const float* __restrict__ u) {
    int row  = blockIdx.x * (blockDim.x >> 5) + (threadIdx.x >> 5);
    int lane = threadIdx.x & 31;
    int total = NU + BQ + NSPLIT * PADROWS;
    if (row >= total) return;

    if (row >= NU + BQ) {
        // zero a pad row of the swizzled s8 table (last tile of each split)
        int pidx = row - (NU + BQ);
        int sp = pidx / PADROWS;
        int r  = (TN - PADROWS) + (pidx % PADROWS);
        size_t base = ((size_t)(sp * NTILES + (NTILES - 1))) << 12;   // u32 units (4096/tile)
        uint32_t off = (tile_off8(r, lane >> 2) >> 2) + (lane & 3);
        g_ubsw[base + off] = 0u;
        return;
    }

    const float* src;
    if (row < NU) src = u + (size_t)row * DIM;
    else          src = q + (size_t)(row - NU) * DIM;
    float4 v = *(const float4*)(src + lane * 4);
    float s = v.x * v.x + v.y * v.y + v.z * v.z + v.w * v.w;
    #pragma unroll
    for (int o = 16; o > 0; o >>= 1) s += __shfl_xor_sync(0xffffffffu, s, o);
    float inv = 1.0f / fmaxf(sqrtf(s), 1e-12f);
    float4 o4 = make_float4(v.x * inv, v.y * inv, v.z * inv, v.w * inv);

    // quantize 4 values -> packed s8 u32
    int i0 = __float2int_rn(o4.x * 127.0f);
    int i1 = __float2int_rn(o4.y * 127.0f);
    int i2 = __float2int_rn(o4.z * 127.0f);
    int i3 = __float2int_rn(o4.w * 127.0f);
    uint32_t pk = (uint32_t)(i0 & 0xff) | ((uint32_t)(i1 & 0xff) << 8) |
                  ((uint32_t)(i2 & 0xff) << 16) | ((uint32_t)(i3 & 0xff) << 24);

    if (row < NU) {
        *(float4*)(g_ue_n + (size_t)row * DIM + lane * 4) = o4;
        int sp = row / NPS, li = row % NPS;
        int tile = li >> 7, r = li & 127;
        size_t base = ((size_t)(sp * NTILES + tile)) << 12;
        uint32_t off = (tile_off8(r, lane >> 2) >> 2) + (lane & 3);
        g_ubsw[base + off] = pk;
    } else {
        int r = row - NU;
        *(float4*)(g_q_n + (size_t)r * DIM + lane * 4) = o4;
        g_qi8[(size_t)r * 32 + lane] = pk;
    }
}

// ---------------- Kernel B: s8 IMMA sims + spill/scan top-12 ----------------
// 512 threads, 16 warps, warp tile 32x32
#define OFF_A    0
#define OFF_B0   16384
#define OFF_B1   32768
#define OFF_SIMS 49152
#define OFF_THR  (OFF_SIMS + 128 * SP_U32 * 4)     // 49152+66560 = 115712
#define OFF_TRIG (OFF_THR + 512)                   // 116224
#define OFF_MBAR (OFF_TRIG + 512)                  // 116736
#define SMEM_BYTES (OFF_MBAR + 64 + 1024)          // ~117.8KB

__global__ __launch_bounds__(512) void cand_kernel() {
    extern __shared__ char sraw[];
    uint32_t sb0 = smem_u32(sraw);
    uint32_t ab = (sb0 + 1023) & ~1023u;
    char* base = sraw + (ab - sb0);

    int* simsu = (int*)(base + OFF_SIMS);
    int* thr   = (int*)(base + OFF_THR);
    int* trig  = (int*)(base + OFF_TRIG);
    const uint32_t MB = ab + OFF_MBAR;

    const int t = threadIdx.x;
    const int lane = t & 31;
    const int w = t >> 5;
    const int wr = w >> 2, wc = w & 3;       // 4x4 warp grid
    const int m0w = wr * 32;
    const int n0w = wc * 32;
    const int q0 = blockIdx.x * TM;
    const int sp = blockIdx.y;
    const int u0 = sp * NPS;

    int topv[CAND]; int topi[CAND];
    #pragma unroll
    for (int p = 0; p < CAND; p++) { topv[p] = INT_MIN_V; topi[p] = 0; }

    if (t == 0) { MBARRIER_INIT(MB, 1); MBARRIER_INIT(MB + 8, 1); }
    for (int i = t; i < TM; i += 512) { thr[i] = INT_MIN_V; trig[i] = 0; }

    // load query tile into swizzled smem (s8, 16KB)
    {
        const uint4* src = (const uint4*)(g_qi8 + (size_t)q0 * 32);
        for (int i = t; i < TM * 8; i += 512) {
            int r = i >> 3, c = i & 7;
            *(uint4*)(base + OFF_A + tile_off8(r, c)) = src[i];
        }
    }
    __syncthreads();

    const uint32_t A_s = ab + OFF_A;
    const uint32_t Bs_[2] = { ab + OFF_B0, ab + OFF_B1 };
    const char* tb = (const char*)g_ubsw + ((size_t)sp * NTILES << 14);

    if (t == 0) {
        MBARRIER_EXPECT_TX(MB,     16384u); bulk_ld(Bs_[0], tb,         16384u, MB);
        MBARRIER_EXPECT_TX(MB + 8, 16384u); bulk_ld(Bs_[1], tb + 16384, 16384u, MB + 8);
    }

    // ldsm addressing (same fragment geometry as f16 16816, chunk = 16B)
    const int a_row0 = m0w + (lane & 15);
    const int b_row0 = n0w + (lane & 7) + ((lane >> 4) << 3);
    const int a_chsel = (lane >> 4);
    const int b_chsel = ((lane >> 3) & 1);

    int ph[2] = {0, 0};
    for (int i = 0; i < NTILES; i++) {
        const int s = i & 1;
        const uint32_t Bs = Bs_[s];
        MBARRIER_WAIT_PARITY(MB + s * 8, ph[s]); ph[s] ^= 1;

        // ---- IMMA: warp tile 32 rows x 32 cols, s32 accum ----
        int acc[2][4][4];
        #pragma unroll
        for (int mi = 0; mi < 2; mi++)
            #pragma unroll
            for (int nf = 0; nf < 4; nf++)
                #pragma unroll
                for (int e = 0; e < 4; e++) acc[mi][nf][e] = 0;

        #pragma unroll
        for (int ks = 0; ks < 4; ks++) {
            uint32_t af[2][4], bf[2][4];
            ldsm_x4(A_s + tile_off8(a_row0,      2 * ks + a_chsel), af[0]);
            ldsm_x4(A_s + tile_off8(a_row0 + 16, 2 * ks + a_chsel), af[1]);
            ldsm_x4(Bs  + tile_off8(b_row0,      2 * ks + b_chsel), bf[0]);
            ldsm_x4(Bs  + tile_off8(b_row0 + 16, 2 * ks + b_chsel), bf[1]);
            #pragma unroll
            for (int g = 0; g < 2; g++) {
                mma_s8(acc[0][g * 2 + 0], af[0], bf[g][0], bf[g][1]);
                mma_s8(acc[1][g * 2 + 0], af[1], bf[g][0], bf[g][1]);
                mma_s8(acc[0][g * 2 + 1], af[0], bf[g][2], bf[g][3]);
                mma_s8(acc[1][g * 2 + 1], af[1], bf[g][2], bf[g][3]);
            }
        }

        // ---- per-row max + threshold trig (exact s32 compare) ----
        #pragma unroll
        for (int mi = 0; mi < 2; mi++)
            #pragma unroll
            for (int h = 0; h < 2; h++) {
                int mx = max(acc[mi][0][2 * h], acc[mi][0][2 * h + 1]);
                #pragma unroll
                for (int nf = 1; nf < 4; nf++)
                    mx = max(mx, max(acc[mi][nf][2 * h], acc[mi][nf][2 * h + 1]));
                mx = max(mx, __shfl_xor_sync(0xffffffffu, mx, 1));
                mx = max(mx, __shfl_xor_sync(0xffffffffu, mx, 2));
                int row = m0w + mi * 16 + (lane >> 2) + h * 8;
                if ((lane & 3) == 0 && mx > thr[row]) trig[row] = 1;   // benign race
            }
        __syncthreads();   // trig visible; B[s] fully consumed

        // ---- spill triggered bands (each warp: its 32-col slice) ----
        {
            int f = trig[m0w + lane];
            unsigned bal = __ballot_sync(0xffffffffu, f != 0);
            if (bal) {
                #pragma unroll
                for (int mi = 0; mi < 2; mi++) {
                    int row = m0w + mi * 16 + (lane >> 2);
                    #pragma unroll
                    for (int nf = 0; nf < 4; nf++) {
                        int cp = wc * 32 + nf * 8 + 2 * (lane & 3);
                        *(int2*)&simsu[row * SP_U32 + cp] =
                            make_int2(acc[mi][nf][0], acc[mi][nf][1]);
                        *(int2*)&simsu[(row + 8) * SP_U32 + cp] =
                            make_int2(acc[mi][nf][2], acc[mi][nf][3]);
                    }
                }
            }
        }
        if (t == 0 && i + 2 < NTILES) {
            MBARRIER_EXPECT_TX(MB + s * 8, 16384u);
            bulk_ld(Bs, tb + ((size_t)(i + 2) << 14), 16384u, MB + s * 8);
        }
        __syncthreads();   // sims visible

        // ---- owner threads (t<128) scan triggered rows ----
        if (t < TM && trig[t]) {
            int nvalid = min(TN, NPS - i * TN);
            int cbase = u0 + i * TN;
            const int* srow = simsu + t * SP_U32;
            for (int c = 0; c < nvalid; c++) {
                int v = srow[c];
                int idx = cbase + c;
                if (v > topv[CAND - 1] ||
                    (v == topv[CAND - 1] && idx < topi[CAND - 1])) {
                    int vv = v, ii = idx;
                    #pragma unroll
                    for (int p = 0; p < CAND; p++) {
                        bool better = (vv > topv[p]) || (vv == topv[p] && ii < topi[p]);
                        if (better) {
                            int tv = topv[p]; topv[p] = vv; vv = tv;
                            int ti = topi[p]; topi[p] = ii; ii = ti;
                        }
                    }
                }
            }
            thr[t] = topv[CAND - 1];
            trig[t] = 0;
        }
        __syncthreads();
    }

    if (t < TM) {
        size_t b = (size_t)(q0 + t) * NCAND + sp * CAND;
        #pragma unroll
        for (int e = 0; e < CAND; e++) g_ci[b + e] = topi[e];
    }
}

// ---------------- Kernel C: exact rescore + select + gather -----------------
__global__ void finalize_kernel(float* __restrict__ out) {
    __shared__ float cv[NCAND];
    __shared__ int   ci[NCAND];
    __shared__ int   sel[TOPK];
    __shared__ float selv[TOPK];

    const int q = blockIdx.x;
    const int t = threadIdx.x;
    const int w = t >> 5, lane = t & 31;

    if (t < NCAND) ci[t] = g_ci[(size_t)q * NCAND + t];
    __syncthreads();

    // exact fp32 rescore: warp w handles candidates [w*12, w*12+12)
    float4 qv = *(const float4*)(g_q_n + (size_t)q * DIM + lane * 4);
    #pragma unroll 1
    for (int cc = 0; cc < CAND; cc++) {
        int idx = ci[w * CAND + cc];
        float4 uv = *(const float4*)(g_ue_n + (size_t)idx * DIM + lane * 4);
        float s = qv.x * uv.x;
        s = fmaf(qv.y, uv.y, s);
        s = fmaf(qv.z, uv.z, s);
        s = fmaf(qv.w, uv.w, s);
        #pragma unroll
        for (int o = 16; o > 0; o >>= 1) s += __shfl_xor_sync(0xffffffffu, s, o);
        if (lane == 0) cv[w * CAND + cc] = s;
    }
    __syncthreads();

    if (t == 0) {
        float bv[K1]; int bi[K1]; int cnt = 0;
        for (int i = 0; i < NCAND; i++) {
            float v = cv[i]; int id = ci[i];
            bool better = (cnt < K1) || (v > bv[K1 - 1]) || (v == bv[K1 - 1] && id < bi[K1 - 1]);
            if (!better) continue;
            int j = (cnt < K1) ? cnt : K1 - 1;
            while (j > 0 && (v > bv[j - 1] || (v == bv[j - 1] && id < bi[j - 1]))) {
                bv[j] = bv[j - 1]; bi[j] = bi[j - 1]; j--;
            }
            bv[j] = v; bi[j] = id;
            if (cnt < K1) cnt++;
        }
        int order[K1]; int nv = 0;
        for (int i = 0; i < K1; i++) if (bv[i] < 0.9999f) order[nv++] = i;
        int oi = nv;
        for (int i = 0; i < K1; i++) if (!(bv[i] < 0.9999f)) order[oi++] = i;
        for (int j = 0; j < TOPK; j++) {
            int pos = (nv > 0) ? order[min(j, nv - 1)] : j;
            sel[j] = bi[pos]; selv[j] = bv[pos];
        }
    }
    __syncthreads();

    float* oute = out;                              // [BQ, TOPK, DIM]
    float* outs = out + (size_t)BQ * TOPK * DIM;    // [BQ, TOPK]
    #pragma unroll
    for (int j = 0; j < TOPK; j++)
        oute[((size_t)q * TOPK + j) * DIM + t] = g_ue_n[(size_t)sel[j] * DIM + t];
    if (t < TOPK) outs[(size_t)q * TOPK + t] = selv[t];
}

// ---------------- launch ----------------------------------------------------
extern "C" void kernel_launch(void* const* d_in, const int* in_sizes, int n_in,
                              void* d_out, int out_size) {
    const float* q = (const float*)d_in[0];
    const float* u = (const float*)d_in[1];
    if (n_in >= 2 && in_sizes[0] != BQ * DIM) { const float* tmp = q; q = u; u = tmp; }
    float* out = (float*)d_out;

    int rows = NU + BQ + NSPLIT * PADROWS;
    prep_kernel<<<(rows + 7) / 8, 256>>>(q, u);

    cudaFuncSetAttribute(cand_kernel, cudaFuncAttributeMaxDynamicSharedMemorySize, SMEM_BYTES);
    cand_kernel<<<dim3(QB, NSPLIT), 512, SMEM_BYTES>>>();

    finalize_kernel<<<BQ, DIM>>>(out);
}